// round 1
// baseline (speedup 1.0000x reference)
#include <cuda_runtime.h>
#include <math.h>

#define B 32
#define T 2048
#define W 10
#define D 5
#define NH 64
#define BT (B*T)

// scratch (no allocations allowed)
__device__ float g_ret[BT];
__device__ float g_vol[BT];
__device__ float g_Hl[BT];

// ---------------- K1: ret + vol (per-batch block scan) ----------------
__global__ void k_scan(const float* __restrict__ F) {
    int b = blockIdx.x;
    int tid = threadIdx.x;
    __shared__ float sh[256];
    int base = tid * 8;
    const float* fb = F + (size_t)b * T * D;
    float lp_prev = (base > 0) ? fb[(base - 1) * D] : 0.f;
    float a[8];
    float run = 0.f;
#pragma unroll
    for (int k = 0; k < 8; k++) {
        int t = base + k;
        float lp = fb[t * D];
        float r = (t == 0) ? 0.f : (lp - lp_prev);
        lp_prev = lp;
        g_ret[b * T + t] = r;
        run += fabsf(r);
        a[k] = run;
    }
    sh[tid] = run;
    __syncthreads();
    float acc = run;
    for (int off = 1; off < 256; off <<= 1) {
        float v = (tid >= off) ? sh[tid - off] : 0.f;
        __syncthreads();
        acc += v;
        sh[tid] = acc;
        __syncthreads();
    }
    float excl = acc - run;
#pragma unroll
    for (int k = 0; k < 8; k++) {
        int t = base + k;
        g_vol[b * T + t] = (excl + a[k]) / ((float)(t + 1) + 1e-8f);
    }
}

// ---------------- K2: windowed H MLP -> H_local ----------------
__global__ void k_hmlp(const float* __restrict__ hw1, const float* __restrict__ hb1,
                       const float* __restrict__ hw2, const float* __restrict__ hb2,
                       const float* __restrict__ hw3, const float* __restrict__ hb3) {
    __shared__ float s1[10 * 32], sb1[32], s2[32 * 32], sb2[32], s3[32];
    __shared__ float sb3;
    int tid = threadIdx.x;
    for (int k = tid; k < 320; k += 256) s1[k] = hw1[k];
    for (int k = tid; k < 1024; k += 256) s2[k] = hw2[k];
    if (tid < 32) { sb1[tid] = hb1[tid]; sb2[tid] = hb2[tid]; s3[tid] = hw3[tid]; }
    if (tid == 0) sb3 = hb3[0];
    __syncthreads();
    const int TW = T - W;
    int gid = blockIdx.x * 256 + tid;
    if (gid >= B * TW) return;
    int b = gid / TW, s = gid - b * TW;
    float rw[10];
#pragma unroll
    for (int j = 0; j < 10; j++) rw[j] = g_ret[b * T + s + j];
    float h1[32];
#pragma unroll
    for (int u = 0; u < 32; u++) {
        float acc = sb1[u];
#pragma unroll
        for (int j = 0; j < 10; j++) acc += rw[j] * s1[j * 32 + u];
        h1[u] = fmaxf(acc, 0.f);
    }
    float o = sb3;
#pragma unroll
    for (int v = 0; v < 32; v++) {
        float acc = sb2[v];
#pragma unroll
        for (int u = 0; u < 32; u++) acc += h1[u] * s2[u * 32 + v];
        o += fmaxf(acc, 0.f) * s3[v];
    }
    float Hval = 0.5f / (1.f + expf(-o));
    g_Hl[b * T + s + W] = Hval;
    if (s == 0) {
        for (int t = 0; t < W; t++) g_Hl[b * T + t] = Hval;
    }
}

// ---------------- K3: main fused kernel ----------------
__global__ void __launch_bounds__(256) k_main(
    const float* __restrict__ F,
    const float* __restrict__ gw1, const float* __restrict__ gb1,
    const float* __restrict__ gw2, const float* __restrict__ gb2,
    const float* __restrict__ p1, const float* __restrict__ p1b,
    const float* __restrict__ p2, const float* __restrict__ p2b,
    const float* __restrict__ p3, const float* __restrict__ p3b,
    const float* __restrict__ p4, const float* __restrict__ p4b,
    const float* __restrict__ w1, const float* __restrict__ b1,
    const float* __restrict__ gamma, const float* __restrict__ beta,
    const float* __restrict__ rmean, const float* __restrict__ rvar,
    const float* __restrict__ w2, const float* __restrict__ b2,
    const float* __restrict__ w3, const float* __restrict__ b3,
    float* __restrict__ out)
{
    __shared__ float s_chunk[64 * 64];
    __shared__ float s_w1[69 * 64];
    __shared__ float s_w2[64 * 32];
    __shared__ float s_gw1[64], s_gb1[32], s_gw2[128], s_gb2[4];
    __shared__ float s_p1b[64], s_p2b[64], s_p3b[64], s_p4b[64];
    __shared__ float s_b1[64], s_gamma[64], s_beta[64], s_rmean[64], s_rvar[64];
    __shared__ float s_b2[32], s_w3[32];
    __shared__ float s_b3;

    int tid = threadIdx.x;
    for (int k = tid; k < 69 * 64; k += 256) s_w1[k] = w1[k];
    for (int k = tid; k < 64 * 32; k += 256) s_w2[k] = w2[k];
    if (tid < 64) {
        s_gw1[tid] = gw1[tid];
        s_p1b[tid] = p1b[tid]; s_p2b[tid] = p2b[tid];
        s_p3b[tid] = p3b[tid]; s_p4b[tid] = p4b[tid];
        s_b1[tid] = b1[tid]; s_gamma[tid] = gamma[tid]; s_beta[tid] = beta[tid];
        s_rmean[tid] = rmean[tid]; s_rvar[tid] = rvar[tid];
    }
    if (tid < 32) { s_gb1[tid] = gb1[tid]; s_b2[tid] = b2[tid]; s_w3[tid] = w3[tid]; }
    if (tid < 128) s_gw2[tid] = gw2[tid];
    if (tid < 4) s_gb2[tid] = gb2[tid];
    if (tid == 0) s_b3 = b3[0];
    __syncthreads();

    int gid = blockIdx.x * 256 + tid;
    int b = gid >> 11;
    int t = gid & (T - 1);
    const float* fb = F + (size_t)b * T * D;

    // ---- level-1/2/3 signature over the length-W increment window ----
    float Sacc[5] = {0.f, 0.f, 0.f, 0.f, 0.f};
    float RA[25], l2f[25], l3f[125];
#pragma unroll
    for (int i = 0; i < 25; i++) { RA[i] = 0.f; l2f[i] = 0.f; }
#pragma unroll
    for (int i = 0; i < 125; i++) l3f[i] = 0.f;

    float rowH[5], rowL[5], featv[5];
#pragma unroll
    for (int e = 0; e < 5; e++) { rowH[e] = fb[t * D + e]; featv[e] = rowH[e]; }

#pragma unroll
    for (int r = W - 1; r >= 0; r--) {
        int i0 = t - W + r;
        bool valid = (i0 >= 0);
        float Dw[5];
#pragma unroll
        for (int e = 0; e < 5; e++) {
            rowL[e] = valid ? fb[i0 * D + e] : 0.f;
            Dw[e] = valid ? (rowH[e] - rowL[e]) : 0.f;
        }
#pragma unroll
        for (int e = 0; e < 5; e++) Sacc[e] += Dw[e];
        // l3f[d,e,f] += Dw[d] * RA[e,f]   (RA = sum_{j>r} A[j])
#pragma unroll
        for (int dd = 0; dd < 5; dd++)
#pragma unroll
            for (int ef = 0; ef < 25; ef++)
                l3f[dd * 25 + ef] += Dw[dd] * RA[ef];
        // A[r] = Dw ⊗ S[r];  l2f += A;  RA += A
#pragma unroll
        for (int e = 0; e < 5; e++)
#pragma unroll
            for (int f = 0; f < 5; f++) {
                float Aef = Dw[e] * Sacc[f];
                l2f[e * 5 + f] += Aef;
                RA[e * 5 + f] += Aef;
            }
#pragma unroll
        for (int e = 0; e < 5; e++) rowH[e] = rowL[e];
    }

    // z vector (local memory; dynamically indexed in GEMM loop)
    float zloc[155];
#pragma unroll
    for (int e = 0; e < 5; e++) zloc[e] = Sacc[e];
#pragma unroll
    for (int i = 0; i < 25; i++) zloc[5 + i] = l2f[i];
#pragma unroll
    for (int i = 0; i < 125; i++) zloc[30 + i] = l3f[i];

    // ---- gate ----
    float Hv = g_Hl[gid], vv = g_vol[gid];
    float L0 = s_gb2[0], L1 = s_gb2[1], L2 = s_gb2[2], L3 = s_gb2[3];
#pragma unroll
    for (int u = 0; u < 32; u++) {
        float gh = fmaxf(Hv * s_gw1[u] + vv * s_gw1[32 + u] + s_gb1[u], 0.f);
        L0 += gh * s_gw2[u * 4 + 0];
        L1 += gh * s_gw2[u * 4 + 1];
        L2 += gh * s_gw2[u * 4 + 2];
        L3 += gh * s_gw2[u * 4 + 3];
    }
    float mx = fmaxf(fmaxf(L0, L1), fmaxf(L2, L3));
    float e0 = expf(L0 - mx), e1 = expf(L1 - mx), e2 = expf(L2 - mx), e3 = expf(L3 - mx);
    float inv = 1.f / (e0 + e1 + e2 + e3);
    float g0 = e0 * inv;
    float g1 = (t >= 1) ? e1 * inv : 0.f;
    float g2 = (t >= 2) ? e2 * inv : 0.f;
    float g3 = (t >= 3) ? e3 * inv : 0.f;

    // ---- sig_repr = sum_k g_k * (z_k @ p_k + p_kb), via SMEM-chunked GEMM ----
    float y[64];
#pragma unroll
    for (int j = 0; j < 64; j++)
        y[j] = g0 * s_p1b[j] + g1 * s_p2b[j] + g2 * s_p3b[j] + g3 * s_p4b[j];

    auto seg = [&](const float* __restrict__ Wg, int nrows, float scale) {
        for (int cs = 0; cs < nrows; cs += 64) {
            int n = min(64, nrows - cs);
            __syncthreads();
            const float4* src = reinterpret_cast<const float4*>(Wg + cs * 64);
            float4* dst = reinterpret_cast<float4*>(s_chunk);
            int n16 = n * 16;
            for (int k = tid; k < n16; k += 256) dst[k] = src[k];
            __syncthreads();
            for (int ii = 0; ii < n; ii++) {
                int i = cs + ii;
                float zi;
                if (i < 155) {
                    zi = zloc[i];
                } else {
                    int idx = i - 155;
                    int aa = idx / 25;
                    int bb = idx - aa * 25;
                    zi = zloc[5 + aa] * zloc[5 + bb];  // l4f on the fly
                }
                zi *= scale;
                const float4* wr = reinterpret_cast<const float4*>(s_chunk + ii * 64);
#pragma unroll
                for (int j4 = 0; j4 < 16; j4++) {
                    float4 wv = wr[j4];
                    y[4 * j4 + 0] += zi * wv.x;
                    y[4 * j4 + 1] += zi * wv.y;
                    y[4 * j4 + 2] += zi * wv.z;
                    y[4 * j4 + 3] += zi * wv.w;
                }
            }
        }
    };
    seg(p1, 5, g0);
    seg(p2, 30, g1);
    seg(p3, 155, g2);
    seg(p4, 780, g3);

    // ---- head: h1 = relu([sig, feat] @ w1 + b1) ----
    float h1[64];
#pragma unroll
    for (int j = 0; j < 64; j++) h1[j] = s_b1[j];
#pragma unroll
    for (int k = 0; k < 64; k++) {
        float v = y[k];
        const float4* wr = reinterpret_cast<const float4*>(s_w1 + k * 64);
#pragma unroll
        for (int j4 = 0; j4 < 16; j4++) {
            float4 wv = wr[j4];
            h1[4 * j4 + 0] += v * wv.x;
            h1[4 * j4 + 1] += v * wv.y;
            h1[4 * j4 + 2] += v * wv.z;
            h1[4 * j4 + 3] += v * wv.w;
        }
    }
#pragma unroll
    for (int e = 0; e < 5; e++) {
        float v = featv[e];
        const float4* wr = reinterpret_cast<const float4*>(s_w1 + (64 + e) * 64);
#pragma unroll
        for (int j4 = 0; j4 < 16; j4++) {
            float4 wv = wr[j4];
            h1[4 * j4 + 0] += v * wv.x;
            h1[4 * j4 + 1] += v * wv.y;
            h1[4 * j4 + 2] += v * wv.z;
            h1[4 * j4 + 3] += v * wv.w;
        }
    }
    // relu then BN
#pragma unroll
    for (int j = 0; j < 64; j++) {
        float hv = fmaxf(h1[j], 0.f);
        h1[j] = s_gamma[j] * (hv - s_rmean[j]) * rsqrtf(s_rvar[j] + 1e-5f) + s_beta[j];
    }
    // h2 = relu(bn @ w2 + b2)
    float h2[32];
#pragma unroll
    for (int c = 0; c < 32; c++) h2[c] = s_b2[c];
#pragma unroll
    for (int j = 0; j < 64; j++) {
        float v = h1[j];
        const float4* wr = reinterpret_cast<const float4*>(s_w2 + j * 32);
#pragma unroll
        for (int c4 = 0; c4 < 8; c4++) {
            float4 wv = wr[c4];
            h2[4 * c4 + 0] += v * wv.x;
            h2[4 * c4 + 1] += v * wv.y;
            h2[4 * c4 + 2] += v * wv.z;
            h2[4 * c4 + 3] += v * wv.w;
        }
    }
    float o = s_b3;
#pragma unroll
    for (int c = 0; c < 32; c++) o += fmaxf(h2[c], 0.f) * s_w3[c];
    out[gid] = 1.5f * tanhf(o);
}

extern "C" void kernel_launch(void* const* d_in, const int* in_sizes, int n_in,
                              void* d_out, int out_size) {
    const float* F    = (const float*)d_in[0];
    const float* hw1  = (const float*)d_in[1];
    const float* hb1  = (const float*)d_in[2];
    const float* hw2  = (const float*)d_in[3];
    const float* hb2  = (const float*)d_in[4];
    const float* hw3  = (const float*)d_in[5];
    const float* hb3  = (const float*)d_in[6];
    const float* gw1  = (const float*)d_in[7];
    const float* gb1  = (const float*)d_in[8];
    const float* gw2  = (const float*)d_in[9];
    const float* gb2  = (const float*)d_in[10];
    const float* p1   = (const float*)d_in[11];
    const float* p1b  = (const float*)d_in[12];
    const float* p2   = (const float*)d_in[13];
    const float* p2b  = (const float*)d_in[14];
    const float* p3   = (const float*)d_in[15];
    const float* p3b  = (const float*)d_in[16];
    const float* p4   = (const float*)d_in[17];
    const float* p4b  = (const float*)d_in[18];
    const float* w1   = (const float*)d_in[19];
    const float* b1   = (const float*)d_in[20];
    const float* gm   = (const float*)d_in[21];
    const float* bt   = (const float*)d_in[22];
    const float* rmean= (const float*)d_in[23];
    const float* rvar = (const float*)d_in[24];
    const float* w2   = (const float*)d_in[25];
    const float* b2   = (const float*)d_in[26];
    const float* w3   = (const float*)d_in[27];
    const float* b3   = (const float*)d_in[28];

    k_scan<<<B, 256>>>(F);
    k_hmlp<<<(B * (T - W) + 255) / 256, 256>>>(hw1, hb1, hw2, hb2, hw3, hb3);
    k_main<<<BT / 256, 256>>>(F, gw1, gb1, gw2, gb2,
                              p1, p1b, p2, p2b, p3, p3b, p4, p4b,
                              w1, b1, gm, bt, rmean, rvar,
                              w2, b2, w3, b3, (float*)d_out);
}

// round 2
// speedup vs baseline: 1.2388x; 1.2388x over previous
#include <cuda_runtime.h>
#include <math.h>

#define B_  32
#define T_  2048
#define W_  10
#define BT_ (B_*T_)
#define NTH 128

typedef unsigned long long u64;

// scratch
__device__ float g_ret[BT_];
__device__ float g_vol[BT_];
__device__ float g_Hl[BT_];

// ---------------- packed f32x2 helpers ----------------
__device__ __forceinline__ u64 pk2(float a, float b) {
    u64 r; asm("mov.b64 %0, {%1, %2};" : "=l"(r) : "f"(a), "f"(b)); return r;
}
__device__ __forceinline__ void fma2(u64 &d, u64 a, u64 b) {
    asm("fma.rn.f32x2 %0, %1, %2, %0;" : "+l"(d) : "l"(a), "l"(b));
}
__device__ __forceinline__ float2 up2(u64 a) {
    float2 f; asm("mov.b64 {%0, %1}, %2;" : "=f"(f.x), "=f"(f.y) : "l"(a)); return f;
}

// y[0..31] (64 cols packed) += wrow[64] * z2
__device__ __forceinline__ void row_acc64(u64* y, const float* wrow, u64 z2) {
    const ulonglong2* p = (const ulonglong2*)wrow;
#pragma unroll
    for (int q = 0; q < 16; q++) {
        ulonglong2 w = p[q];
        fma2(y[2*q+0], w.x, z2);
        fma2(y[2*q+1], w.y, z2);
    }
}
// y[0..15] (32 cols packed) += wrow[32] * z2
__device__ __forceinline__ void row_acc32(u64* y, const float* wrow, u64 z2) {
    const ulonglong2* p = (const ulonglong2*)wrow;
#pragma unroll
    for (int q = 0; q < 8; q++) {
        ulonglong2 w = p[q];
        fma2(y[2*q+0], w.x, z2);
        fma2(y[2*q+1], w.y, z2);
    }
}

__device__ __forceinline__ void stage_load(float* dst, const float* __restrict__ src,
                                           int nfloats, int tid) {
    const float4* s4 = (const float4*)src;
    float4* d4 = (float4*)dst;
    for (int k = tid; k < (nfloats >> 2); k += NTH) d4[k] = s4[k];
}

// ---------------- K1: ret + vol ----------------
__global__ void k_scan(const float* __restrict__ F) {
    int b = blockIdx.x;
    int tid = threadIdx.x;
    __shared__ float sh[256];
    int base = tid * 8;
    const float* fb = F + (size_t)b * T_ * 5;
    float lp_prev = (base > 0) ? fb[(base - 1) * 5] : 0.f;
    float a[8];
    float run = 0.f;
#pragma unroll
    for (int k = 0; k < 8; k++) {
        int t = base + k;
        float lp = fb[t * 5];
        float r = (t == 0) ? 0.f : (lp - lp_prev);
        lp_prev = lp;
        g_ret[b * T_ + t] = r;
        run += fabsf(r);
        a[k] = run;
    }
    sh[tid] = run;
    __syncthreads();
    float acc = run;
    for (int off = 1; off < 256; off <<= 1) {
        float v = (tid >= off) ? sh[tid - off] : 0.f;
        __syncthreads();
        acc += v;
        sh[tid] = acc;
        __syncthreads();
    }
    float excl = acc - run;
#pragma unroll
    for (int k = 0; k < 8; k++) {
        int t = base + k;
        g_vol[b * T_ + t] = (excl + a[k]) / ((float)(t + 1) + 1e-8f);
    }
}

// ---------------- K2: windowed H MLP ----------------
__global__ void k_hmlp(const float* __restrict__ hw1, const float* __restrict__ hb1,
                       const float* __restrict__ hw2, const float* __restrict__ hb2,
                       const float* __restrict__ hw3, const float* __restrict__ hb3) {
    __shared__ float s1[10 * 32], sb1[32], s2[32 * 32], sb2[32], s3[32];
    __shared__ float sb3;
    int tid = threadIdx.x;
    for (int k = tid; k < 320; k += 256) s1[k] = hw1[k];
    for (int k = tid; k < 1024; k += 256) s2[k] = hw2[k];
    if (tid < 32) { sb1[tid] = hb1[tid]; sb2[tid] = hb2[tid]; s3[tid] = hw3[tid]; }
    if (tid == 0) sb3 = hb3[0];
    __syncthreads();
    const int TW = T_ - W_;
    int gid = blockIdx.x * 256 + tid;
    if (gid >= B_ * TW) return;
    int b = gid / TW, s = gid - b * TW;
    float rw[10];
#pragma unroll
    for (int j = 0; j < 10; j++) rw[j] = g_ret[b * T_ + s + j];
    float h1[32];
#pragma unroll
    for (int u = 0; u < 32; u++) {
        float acc = sb1[u];
#pragma unroll
        for (int j = 0; j < 10; j++) acc += rw[j] * s1[j * 32 + u];
        h1[u] = fmaxf(acc, 0.f);
    }
    float o = sb3;
#pragma unroll
    for (int v = 0; v < 32; v++) {
        float acc = sb2[v];
#pragma unroll
        for (int u = 0; u < 32; u++) acc += h1[u] * s2[u * 32 + v];
        o += fmaxf(acc, 0.f) * s3[v];
    }
    float Hval = 0.5f / (1.f + expf(-o));
    g_Hl[b * T_ + s + W_] = Hval;
    if (s == 0) {
        for (int t = 0; t < W_; t++) g_Hl[b * T_ + t] = Hval;
    }
}

// ---------------- SMEM layout (float offsets, dynamic smem) ----------------
#define SM_DWS   0        // 50*128 = 6400
#define SM_L2S   6400     // 25*128 = 3200
#define SM_STG   9600     // 4800 staging
#define SM_GW1   14400
#define SM_GB1   14464
#define SM_GW2   14496
#define SM_GB2   14624
#define SM_P1B   14628
#define SM_P2B   14692
#define SM_P3B   14756
#define SM_P4B   14820
#define SM_B1    14884
#define SM_GAMMA 14948
#define SM_BETA  15012
#define SM_RMEAN 15076
#define SM_RVAR  15140
#define SM_B2    15204
#define SM_W3    15236
#define SM_B3    15268
#define SM_FLOATS 15280
#define SMEM_BYTES (SM_FLOATS * 4)

// ---------------- K3: main fused kernel ----------------
__global__ void __launch_bounds__(NTH) k_main(
    const float* __restrict__ F,
    const float* __restrict__ gw1, const float* __restrict__ gb1,
    const float* __restrict__ gw2, const float* __restrict__ gb2,
    const float* __restrict__ p1,  const float* __restrict__ p1b,
    const float* __restrict__ p2,  const float* __restrict__ p2b,
    const float* __restrict__ p3,  const float* __restrict__ p3b,
    const float* __restrict__ p4,  const float* __restrict__ p4b,
    const float* __restrict__ w1,  const float* __restrict__ b1,
    const float* __restrict__ gamma, const float* __restrict__ beta,
    const float* __restrict__ rmean, const float* __restrict__ rvar,
    const float* __restrict__ w2,  const float* __restrict__ b2,
    const float* __restrict__ w3,  const float* __restrict__ b3,
    float* __restrict__ out)
{
    extern __shared__ float sm[];
    int tid = threadIdx.x;
    float* dws = sm + SM_DWS;
    float* l2s = sm + SM_L2S;
    float* stg = sm + SM_STG;

    // small persistent params
    if (tid < 64) {
        sm[SM_GW1 + tid] = gw1[tid];
        sm[SM_P1B + tid] = p1b[tid]; sm[SM_P2B + tid] = p2b[tid];
        sm[SM_P3B + tid] = p3b[tid]; sm[SM_P4B + tid] = p4b[tid];
        sm[SM_B1 + tid] = b1[tid]; sm[SM_GAMMA + tid] = gamma[tid];
        sm[SM_BETA + tid] = beta[tid]; sm[SM_RMEAN + tid] = rmean[tid];
        sm[SM_RVAR + tid] = rvar[tid];
    }
    if (tid < 32) { sm[SM_GB1 + tid] = gb1[tid]; sm[SM_B2 + tid] = b2[tid]; sm[SM_W3 + tid] = w3[tid]; }
    if (tid < 128) sm[SM_GW2 + tid] = gw2[tid];
    if (tid < 4)  sm[SM_GB2 + tid] = gb2[tid];
    if (tid == 0) sm[SM_B3] = b3[0];

    int gid = blockIdx.x * NTH + tid;
    int b = gid >> 11;
    int t = gid & (T_ - 1);
    const float* fb = F + (size_t)b * T_ * 5;

    // ---- initial signature pass: Dw window -> SMEM (private lane), S, l2f ----
    float S[5] = {0.f, 0.f, 0.f, 0.f, 0.f};
    float l2f[25];
#pragma unroll
    for (int i = 0; i < 25; i++) l2f[i] = 0.f;
    {
        float rowH[5];
#pragma unroll
        for (int e = 0; e < 5; e++) rowH[e] = fb[t * 5 + e];
#pragma unroll
        for (int r = W_ - 1; r >= 0; r--) {
            int i0 = t - W_ + r;
            bool valid = (i0 >= 0);
            float Dw[5], rowL[5];
#pragma unroll
            for (int e = 0; e < 5; e++) {
                rowL[e] = valid ? fb[i0 * 5 + e] : 0.f;
                Dw[e] = valid ? (rowH[e] - rowL[e]) : 0.f;
                dws[(r * 5 + e) * NTH + tid] = Dw[e];
            }
#pragma unroll
            for (int e = 0; e < 5; e++) S[e] += Dw[e];
#pragma unroll
            for (int e = 0; e < 5; e++)
#pragma unroll
                for (int f = 0; f < 5; f++) l2f[e * 5 + f] += Dw[e] * S[f];
#pragma unroll
            for (int e = 0; e < 5; e++) rowH[e] = rowL[e];
        }
#pragma unroll
        for (int i = 0; i < 25; i++) l2s[i * NTH + tid] = l2f[i];
    }
    __syncthreads();  // small params visible

    // ---- gate ----
    float Hv = g_Hl[gid], vv = g_vol[gid];
    float L0 = sm[SM_GB2 + 0], L1 = sm[SM_GB2 + 1], L2 = sm[SM_GB2 + 2], L3 = sm[SM_GB2 + 3];
#pragma unroll
    for (int u = 0; u < 32; u++) {
        float gh = fmaxf(Hv * sm[SM_GW1 + u] + vv * sm[SM_GW1 + 32 + u] + sm[SM_GB1 + u], 0.f);
        L0 += gh * sm[SM_GW2 + u * 4 + 0];
        L1 += gh * sm[SM_GW2 + u * 4 + 1];
        L2 += gh * sm[SM_GW2 + u * 4 + 2];
        L3 += gh * sm[SM_GW2 + u * 4 + 3];
    }
    float mx = fmaxf(fmaxf(L0, L1), fmaxf(L2, L3));
    float e0 = expf(L0 - mx), e1 = expf(L1 - mx), e2 = expf(L2 - mx), e3 = expf(L3 - mx);
    float inv = 1.f / (e0 + e1 + e2 + e3);
    float g0 = e0 * inv;
    float g1 = (t >= 1) ? e1 * inv : 0.f;
    float g2 = (t >= 2) ? e2 * inv : 0.f;
    float g3 = (t >= 3) ? e3 * inv : 0.f;

    // ---- y init: gated biases ----
    u64 y[32];
    {
        u64 gp0 = pk2(g0, g0), gp1 = pk2(g1, g1), gp2 = pk2(g2, g2), gp3 = pk2(g3, g3);
        const u64* pb1 = (const u64*)(sm + SM_P1B);
        const u64* pb2 = (const u64*)(sm + SM_P2B);
        const u64* pb3 = (const u64*)(sm + SM_P3B);
        const u64* pb4 = (const u64*)(sm + SM_P4B);
#pragma unroll
        for (int q = 0; q < 32; q++) {
            u64 acc = 0ull;  // (0.f, 0.f)
            fma2(acc, pb1[q], gp0);
            fma2(acc, pb2[q], gp1);
            fma2(acc, pb3[q], gp2);
            fma2(acc, pb4[q], gp3);
            y[q] = acc;
        }
    }

    // ---- PHASE A: lvl1 rows (i=0..4) across all 4 matrices ----
    __syncthreads();
    stage_load(stg +   0, p1, 320, tid);
    stage_load(stg + 320, p2, 320, tid);
    stage_load(stg + 640, p3, 320, tid);
    stage_load(stg + 960, p4, 320, tid);
    __syncthreads();
#pragma unroll
    for (int i = 0; i < 5; i++) {
        float zi = S[i];
        float a0 = zi * g0, a1 = zi * g1, a2 = zi * g2, a3 = zi * g3;
        row_acc64(y, stg +       i * 64, pk2(a0, a0));
        row_acc64(y, stg + 320 + i * 64, pk2(a1, a1));
        row_acc64(y, stg + 640 + i * 64, pk2(a2, a2));
        row_acc64(y, stg + 960 + i * 64, pk2(a3, a3));
    }

    // ---- PHASE B: l2 rows (i=0..24) across p2,p3,p4 ----
    __syncthreads();
    stage_load(stg +    0, p2 + 5 * 64, 1600, tid);
    stage_load(stg + 1600, p3 + 5 * 64, 1600, tid);
    stage_load(stg + 3200, p4 + 5 * 64, 1600, tid);
    __syncthreads();
#pragma unroll 5
    for (int i = 0; i < 25; i++) {
        float zi = l2s[i * NTH + tid];
        float a1 = zi * g1, a2 = zi * g2, a3 = zi * g3;
        row_acc64(y, stg +        i * 64, pk2(a1, a1));
        row_acc64(y, stg + 1600 + i * 64, pk2(a2, a2));
        row_acc64(y, stg + 3200 + i * 64, pk2(a3, a3));
    }

    // ---- PHASE C: l3 rows in 5 chunks (dd = leading index), replayed recurrence ----
    for (int dd = 0; dd < 5; dd++) {
        __syncthreads();
        stage_load(stg +    0, p3 + (30 + dd * 25) * 64, 1600, tid);
        stage_load(stg + 1600, p4 + (30 + dd * 25) * 64, 1600, tid);
        __syncthreads();
        float S2[5] = {0.f, 0.f, 0.f, 0.f, 0.f};
        float RA[25], l3c[25];
#pragma unroll
        for (int i = 0; i < 25; i++) { RA[i] = 0.f; l3c[i] = 0.f; }
        for (int r = W_ - 1; r >= 0; r--) {
            float Dw[5];
#pragma unroll
            for (int e = 0; e < 5; e++) Dw[e] = dws[(r * 5 + e) * NTH + tid];
#pragma unroll
            for (int e = 0; e < 5; e++) S2[e] += Dw[e];
            float dwd = dws[(r * 5 + dd) * NTH + tid];
#pragma unroll
            for (int i = 0; i < 25; i++) l3c[i] += dwd * RA[i];
#pragma unroll
            for (int e = 0; e < 5; e++)
#pragma unroll
                for (int f = 0; f < 5; f++) RA[e * 5 + f] += Dw[e] * S2[f];
        }
#pragma unroll
        for (int j = 0; j < 25; j++) {
            float z = l3c[j];
            float a2 = z * g2, a3 = z * g3;
            row_acc64(y, stg +        j * 64, pk2(a2, a2));
            row_acc64(y, stg + 1600 + j * 64, pk2(a3, a3));
        }
    }

    // ---- PHASE D: l4 rows (a,b in 0..24), p4 only ----
    for (int a = 0; a < 25; a++) {
        __syncthreads();
        stage_load(stg, p4 + (155 + a * 25) * 64, 1600, tid);
        __syncthreads();
        float la = l2s[a * NTH + tid] * g3;
#pragma unroll 5
        for (int bb = 0; bb < 25; bb++) {
            float zz = la * l2s[bb * NTH + tid];
            row_acc64(y, stg + bb * 64, pk2(zz, zz));
        }
    }

    // ---- HEAD: h1 = relu([y, feat] @ w1 + b1) ----
    __syncthreads();
    stage_load(stg, w1, 69 * 64, tid);
    __syncthreads();
    u64 h1p[32];
    {
        const u64* b1p = (const u64*)(sm + SM_B1);
#pragma unroll
        for (int q = 0; q < 32; q++) h1p[q] = b1p[q];
    }
#pragma unroll
    for (int q = 0; q < 32; q++) {
        float2 f = up2(y[q]);
        row_acc64(h1p, stg + (2 * q) * 64,     pk2(f.x, f.x));
        row_acc64(h1p, stg + (2 * q + 1) * 64, pk2(f.y, f.y));
    }
#pragma unroll
    for (int e = 0; e < 5; e++) {
        float v = F[(size_t)gid * 5 + e];
        row_acc64(h1p, stg + (64 + e) * 64, pk2(v, v));
    }

    // ---- BN + h2 = relu(bn @ w2 + b2) ----
    __syncthreads();
    stage_load(stg, w2, 64 * 32, tid);
    __syncthreads();
    u64 h2p[16];
    {
        const u64* b2p = (const u64*)(sm + SM_B2);
#pragma unroll
        for (int q = 0; q < 16; q++) h2p[q] = b2p[q];
    }
#pragma unroll
    for (int q = 0; q < 32; q++) {
        float2 h = up2(h1p[q]);
        int j0 = 2 * q;
        float hv = fmaxf(h.x, 0.f);
        float bn0 = sm[SM_GAMMA + j0] * (hv - sm[SM_RMEAN + j0]) * rsqrtf(sm[SM_RVAR + j0] + 1e-5f) + sm[SM_BETA + j0];
        row_acc32(h2p, stg + j0 * 32, pk2(bn0, bn0));
        hv = fmaxf(h.y, 0.f);
        float bn1 = sm[SM_GAMMA + j0 + 1] * (hv - sm[SM_RMEAN + j0 + 1]) * rsqrtf(sm[SM_RVAR + j0 + 1] + 1e-5f) + sm[SM_BETA + j0 + 1];
        row_acc32(h2p, stg + (j0 + 1) * 32, pk2(bn1, bn1));
    }
    float o = sm[SM_B3];
#pragma unroll
    for (int q = 0; q < 16; q++) {
        float2 h = up2(h2p[q]);
        o += fmaxf(h.x, 0.f) * sm[SM_W3 + 2 * q] + fmaxf(h.y, 0.f) * sm[SM_W3 + 2 * q + 1];
    }
    out[gid] = 1.5f * tanhf(o);
}

extern "C" void kernel_launch(void* const* d_in, const int* in_sizes, int n_in,
                              void* d_out, int out_size) {
    const float* F    = (const float*)d_in[0];
    const float* hw1  = (const float*)d_in[1];
    const float* hb1  = (const float*)d_in[2];
    const float* hw2  = (const float*)d_in[3];
    const float* hb2  = (const float*)d_in[4];
    const float* hw3  = (const float*)d_in[5];
    const float* hb3  = (const float*)d_in[6];
    const float* gw1  = (const float*)d_in[7];
    const float* gb1  = (const float*)d_in[8];
    const float* gw2  = (const float*)d_in[9];
    const float* gb2  = (const float*)d_in[10];
    const float* p1   = (const float*)d_in[11];
    const float* p1b  = (const float*)d_in[12];
    const float* p2   = (const float*)d_in[13];
    const float* p2b  = (const float*)d_in[14];
    const float* p3   = (const float*)d_in[15];
    const float* p3b  = (const float*)d_in[16];
    const float* p4   = (const float*)d_in[17];
    const float* p4b  = (const float*)d_in[18];
    const float* w1   = (const float*)d_in[19];
    const float* b1   = (const float*)d_in[20];
    const float* gm   = (const float*)d_in[21];
    const float* bt   = (const float*)d_in[22];
    const float* rmean= (const float*)d_in[23];
    const float* rvar = (const float*)d_in[24];
    const float* w2   = (const float*)d_in[25];
    const float* b2   = (const float*)d_in[26];
    const float* w3   = (const float*)d_in[27];
    const float* b3   = (const float*)d_in[28];

    cudaFuncSetAttribute(k_main, cudaFuncAttributeMaxDynamicSharedMemorySize, SMEM_BYTES);

    k_scan<<<B_, 256>>>(F);
    k_hmlp<<<(B_ * (T_ - W_) + 255) / 256, 256>>>(hw1, hb1, hw2, hb2, hw3, hb3);
    k_main<<<BT_ / NTH, NTH, SMEM_BYTES>>>(F, gw1, gb1, gw2, gb2,
                                           p1, p1b, p2, p2b, p3, p3b, p4, p4b,
                                           w1, b1, gm, bt, rmean, rvar,
                                           w2, b2, w3, b3, (float*)d_out);
}